// round 15
// baseline (speedup 1.0000x reference)
#include <cuda_runtime.h>
#include <cuda_fp16.h>
#include <math.h>

#define NNODES 50000
#define KNB 32
#define NLAT 10
#define NB 4
#define NCHUNK 10
#define QROW 12500        // float4 quads per 50000-float row
#define QCHW 1250         // quads per split-K chunk (12500/10)
#define PACKB 196         // pack blocks (ceil(50000/256))
#define GEMVB 250         // gemv blocks (25 u-groups x 10 chunks)
#define GATHER_BLOCKS 782 // ceil(50000 / 64)
#define WARMQ 5780        // float4 quads of MLP weights to stream through L2

__device__ uint4 g_decwr[NNODES * 2];       // fp16-packed dec_w rows (32B/row)
__device__ float g_part[NCHUNK * 800];      // GEMV partials [chunk][b*200+u]
__device__ float g_Htab[NB * 256];          // sigmoid table per (b, cluster)
__device__ float g_e[NB * NLAT];            // latent e
__device__ float g_sink[WARMQ];             // L2-warm sink (deterministic)
__device__ unsigned g_done;                 // gemv-block completion counter

__device__ __forceinline__ float2 h2f(unsigned u) {
    __half2 h = *reinterpret_cast<__half2*>(&u);
    return __half22float2(h);
}

__device__ __forceinline__ float fsigmoid(float v) {
    return 1.0f / (1.0f + __expf(-v));
}

// ---------------------------------------------------------------- k_front
// Blocks 0..195:   pack dec_w to fp16 + stream MLP weights through L2.
// Blocks 196..445: gemv split-K partials (warp-per-u, 8 u per block).
// LAST gemv block to finish additionally runs the whole tiny-MLP chain
// (reduce+silu -> e -> h1 -> h2 -> h3+sigmoid table) with warm L2/I$.
__global__ __launch_bounds__(256) void k_front(
        const float* __restrict__ x,   const float* __restrict__ w,
        const float* __restrict__ dec_w,
        const float* __restrict__ enc1_b,
        const float* __restrict__ enc2_w, const float* __restrict__ enc2_b,
        const float* __restrict__ h1_w,  const float* __restrict__ h1_b,
        const float* __restrict__ h2_w,  const float* __restrict__ h2_b,
        const float* __restrict__ h3_w,  const float* __restrict__ h3_b) {
    int tid = threadIdx.x;

    if (blockIdx.x < PACKB) {
        // ------------------------------------------------ pack + L2 warm
        int n = blockIdx.x * 256 + tid;
        if (n < NNODES) {
            const float2* rp = (const float2*)(dec_w + n * NLAT);
            float2 a = __ldg(rp), b = __ldg(rp + 1), c = __ldg(rp + 2),
                   d = __ldg(rp + 3), e = __ldg(rp + 4);
            __half2 p0 = __float22half2_rn(a), p1 = __float22half2_rn(b),
                    p2 = __float22half2_rn(c), p3 = __float22half2_rn(d),
                    p4 = __float22half2_rn(e);
            uint4 lo = make_uint4(*(unsigned*)&p0, *(unsigned*)&p1,
                                  *(unsigned*)&p2, *(unsigned*)&p3);
            g_decwr[2 * n] = lo;
            ((uint2*)g_decwr)[4 * n + 2] = make_uint2(*(unsigned*)&p4, 0u);
        }
        if (n < WARMQ) {
            float4 v;
            if (n < 4096)       v = __ldg((const float4*)h3_w + n);
            else if (n < 5120)  v = __ldg((const float4*)h2_w + (n - 4096));
            else if (n < 5620)  v = __ldg((const float4*)enc2_w + (n - 5120));
            else                v = __ldg((const float4*)h1_w + (n - 5620));
            g_sink[n] = (v.x + v.y) + (v.z + v.w);
        }
        return;
    }

    // ---------------------------------------------------- gemv block
    int gid = blockIdx.x - PACKB;
    int warp = tid >> 5, lane = tid & 31;
    int ug = gid % 25, c = gid / 25;
    int u = ug * 8 + warp;
    int q0 = c * QCHW;

    const float4* x4 = (const float4*)x;
    const float4* w4 = (const float4*)w + (size_t)u * QROW;

    float a0 = 0.0f, a1 = 0.0f, a2 = 0.0f, a3 = 0.0f;

#pragma unroll 2
    for (int q = q0 + lane; q < q0 + QCHW; q += 32) {
        float4 wv = __ldg(w4 + q);
        float4 x0 = __ldg(x4 + q);
        float4 x1 = __ldg(x4 + QROW + q);
        float4 x2 = __ldg(x4 + 2 * QROW + q);
        float4 x3 = __ldg(x4 + 3 * QROW + q);
        a0 = fmaf(wv.x, x0.x, a0); a0 = fmaf(wv.y, x0.y, a0);
        a0 = fmaf(wv.z, x0.z, a0); a0 = fmaf(wv.w, x0.w, a0);
        a1 = fmaf(wv.x, x1.x, a1); a1 = fmaf(wv.y, x1.y, a1);
        a1 = fmaf(wv.z, x1.z, a1); a1 = fmaf(wv.w, x1.w, a1);
        a2 = fmaf(wv.x, x2.x, a2); a2 = fmaf(wv.y, x2.y, a2);
        a2 = fmaf(wv.z, x2.z, a2); a2 = fmaf(wv.w, x2.w, a2);
        a3 = fmaf(wv.x, x3.x, a3); a3 = fmaf(wv.y, x3.y, a3);
        a3 = fmaf(wv.z, x3.z, a3); a3 = fmaf(wv.w, x3.w, a3);
    }

#pragma unroll
    for (int o = 16; o; o >>= 1) {
        a0 += __shfl_down_sync(0xffffffffu, a0, o);
        a1 += __shfl_down_sync(0xffffffffu, a1, o);
        a2 += __shfl_down_sync(0xffffffffu, a2, o);
        a3 += __shfl_down_sync(0xffffffffu, a3, o);
    }
    if (lane == 0) {
        float* p = g_part + c * 800 + u;
        p[0]   = a0;
        p[200] = a1;
        p[400] = a2;
        p[600] = a3;
        __threadfence();              // make partials globally visible
    }
    __syncthreads();                  // order all warps' fences before atomic

    __shared__ bool s_last;
    if (tid == 0) s_last = (atomicAdd(&g_done, 1u) == GEMVB - 1);
    __syncthreads();
    if (!s_last) return;
    __threadfence();                  // acquire: see all blocks' partials

    // ---------------------------------------------------- MLP chain tail
    __shared__ float sz[800];
    __shared__ float se[40];
    __shared__ float sh1[256];
    __shared__ float sh2[256];

    if (tid < 200) {
        const float4* p = (const float4*)g_part;
        float4 s = p[tid];
#pragma unroll
        for (int cc = 1; cc < NCHUNK; cc++) {
            float4 v = p[cc * 200 + tid];
            s.x += v.x; s.y += v.y; s.z += v.z; s.w += v.w;
        }
        float sv[4] = {s.x, s.y, s.z, s.w};
#pragma unroll
        for (int j = 0; j < 4; j++) {
            int idx = tid * 4 + j;
            float t = sv[j] + enc1_b[idx % 200];
            sz[idx] = t * fsigmoid(t);              // silu
        }
    }
    __syncthreads();

    if (tid < 160) {
        int g = tid >> 2, r = tid & 3;
        int b = g / 10, v = g - b * 10;
        const float4* wrow = (const float4*)(enc2_w + v * 200);
        const float* zb = sz + b * 200;
        float s = 0.0f;
        for (int q = r; q < 50; q += 4) {
            float4 wv = __ldg(wrow + q);
            s = fmaf(wv.x, zb[4 * q + 0], s);
            s = fmaf(wv.y, zb[4 * q + 1], s);
            s = fmaf(wv.z, zb[4 * q + 2], s);
            s = fmaf(wv.w, zb[4 * q + 3], s);
        }
#pragma unroll
        for (int o = 2; o; o >>= 1) s += __shfl_down_sync(0xffffffffu, s, o, 4);
        if (r == 0) {
            s += enc2_b[v];
            se[g] = s;
            g_e[g] = s;
        }
    }
    __syncthreads();

    {
        int b = tid >> 6, m = tid & 63;
        float s = h1_b[m];
#pragma unroll
        for (int v = 0; v < 10; v++)
            s = fmaf(se[b * 10 + v], h1_w[m * 10 + v], s);
        sh1[tid] = s * fsigmoid(s);
    }
    __syncthreads();

    {
        int b = tid >> 6, m = tid & 63;
        const float4* wrow = (const float4*)(h2_w + m * 64);
        const float* hb = sh1 + b * 64;
        float s = h2_b[m];
#pragma unroll
        for (int q = 0; q < 16; q++) {
            float4 wv = __ldg(wrow + q);
            s = fmaf(wv.x, hb[4 * q + 0], s);
            s = fmaf(wv.y, hb[4 * q + 1], s);
            s = fmaf(wv.z, hb[4 * q + 2], s);
            s = fmaf(wv.w, hb[4 * q + 3], s);
        }
        sh2[tid] = s * fsigmoid(s);
    }
    __syncthreads();

#pragma unroll
    for (int i = 0; i < 4; i++) {
        int idx = i * 256 + tid;
        int b = idx >> 8, cc = idx & 255;
        const float4* wrow = (const float4*)(h3_w + cc * 64);
        const float* hb = sh2 + b * 64;
        float s = h3_b[cc];
#pragma unroll
        for (int q = 0; q < 16; q++) {
            float4 wv = __ldg(wrow + q);
            s = fmaf(wv.x, hb[4 * q + 0], s);
            s = fmaf(wv.y, hb[4 * q + 1], s);
            s = fmaf(wv.z, hb[4 * q + 2], s);
            s = fmaf(wv.w, hb[4 * q + 3], s);
        }
        g_Htab[idx] = fsigmoid(0.005f * s);
    }

    if (tid == 0) g_done = 0;         // reset for next graph replay
}

// ---------------------------------------------------------------- k_back
// Gather + final combine fused: 4 lanes per node build A/Bv/S0/d2max,
// butterfly-share, then lane sub==b does the closed-form combine for
// batch b and writes out[b*NNODES+node]. No stats round-trip.
__global__ __launch_bounds__(256) void k_back(const int* __restrict__ nb_id,
                                              const float* __restrict__ nb_dist,
                                              const int* __restrict__ labels,
                                              const float* __restrict__ dec_b,
                                              const float* __restrict__ Bparam,
                                              const float* __restrict__ dec_w,
                                              float* __restrict__ out) {
    int tid = threadIdx.x;
    int sub = tid & 3;
    int node = blockIdx.x * 64 + (tid >> 2);
    bool valid = (node < NNODES);
    int cnode = valid ? node : (NNODES - 1);

    float A[NLAT], Bv[NLAT];
#pragma unroll
    for (int l = 0; l < NLAT; l++) { A[l] = 0.0f; Bv[l] = 0.0f; }
    float S0 = 0.0f, d2max = 0.0f;

    const int4*   idp = (const int4*)(nb_id + cnode * KNB) + sub * 2;
    const float4* dp  = (const float4*)(nb_dist + cnode * KNB) + sub * 2;
#pragma unroll
    for (int kq = 0; kq < 2; kq++) {
        int4   iv = __ldg(idp + kq);
        float4 dv = __ldg(dp + kq);
        int   ida[4] = {iv.x, iv.y, iv.z, iv.w};
        float da[4]  = {dv.x, dv.y, dv.z, dv.w};
#pragma unroll
        for (int j = 0; j < 4; j++) {
            float d2 = da[j] * da[j];
            S0 += d2;
            d2max = fmaxf(d2max, d2);
            uint4 lo = __ldg(&g_decwr[2 * ida[j]]);
            uint2 hi = __ldg((const uint2*)g_decwr + 4 * ida[j] + 2);
            float2 f0 = h2f(lo.x), f1 = h2f(lo.y), f2 = h2f(lo.z),
                   f3 = h2f(lo.w), f4 = h2f(hi.x);
            float r[NLAT] = {f0.x, f0.y, f1.x, f1.y, f2.x,
                             f2.y, f3.x, f3.y, f4.x, f4.y};
#pragma unroll
            for (int l = 0; l < NLAT; l++) {
                A[l] += r[l];
                Bv[l] = fmaf(d2, r[l], Bv[l]);
            }
        }
    }

    // butterfly: all 4 lanes end with the full per-node sums
#pragma unroll
    for (int off = 1; off < 4; off <<= 1) {
#pragma unroll
        for (int l = 0; l < NLAT; l++) {
            A[l]  += __shfl_xor_sync(0xffffffffu, A[l],  off);
            Bv[l] += __shfl_xor_sync(0xffffffffu, Bv[l], off);
        }
        S0 += __shfl_xor_sync(0xffffffffu, S0, off);
        d2max = fmaxf(d2max, __shfl_xor_sync(0xffffffffu, d2max, off));
    }

    if (!valid) return;

    // lane sub handles batch b = sub
    int b = sub;
    int label = __ldg(&labels[node]);
    float Bp = __ldg(Bparam);
    float invB2 = __fdividef(1.0f, Bp * Bp);
    float H = __ldg(&g_Htab[b * 256 + label]);
    float base = 1.0f - 0.5f * H;
    float ib = __fdividef(1.0f, base * base);
    float ib2 = ib * ib;
    float ib4 = ib2 * ib2;
    float inv9 = invB2 * ib4 * ib4 * ib2;

    float o = 0.0f;
    if (inv9 * d2max <= 1.0f) {
        float iw = invB2;
#pragma unroll
        for (int l = 0; l < NLAT; l++) {
            iw *= ib;
            float s = fmaf(-iw, S0, (float)KNB);
            float t = fmaf(-iw, Bv[l], A[l]);
            o = fmaf(__ldg(&g_e[b * NLAT + l]), __fdividef(t, s), o);
        }
    } else {
        // exact fallback with clamping (fp32 dec_w; practically never taken)
        float iw = invB2;
        for (int l = 0; l < NLAT; l++) {
            iw *= ib;
            float ss = 0.0f, tt = 0.0f;
            for (int k = 0; k < KNB; k++) {
                int id = __ldg(nb_id + node * KNB + k);
                float d = __ldg(nb_dist + node * KNB + k);
                float d2 = d * d;
                float win = fmaxf(0.0f, fmaf(-iw, d2, 1.0f));
                ss += win;
                tt = fmaf(__ldg(&dec_w[id * NLAT + l]), win, tt);
            }
            o = fmaf(__ldg(&g_e[b * NLAT + l]), __fdividef(tt, ss), o);
        }
    }

    out[b * NNODES + node] = o + __ldg(&dec_b[node]);
}

// ---------------------------------------------------------------- launch
extern "C" void kernel_launch(void* const* d_in, const int* in_sizes, int n_in,
                              void* d_out, int out_size) {
    const float* x       = (const float*)d_in[0];
    const int*   nb_id   = (const int*)  d_in[1];
    const float* nb_dist = (const float*)d_in[2];
    const int*   labels  = (const int*)  d_in[3];
    const float* enc1_w  = (const float*)d_in[4];
    const float* enc1_b  = (const float*)d_in[5];
    const float* enc2_w  = (const float*)d_in[6];
    const float* enc2_b  = (const float*)d_in[7];
    const float* dec_w   = (const float*)d_in[8];
    const float* dec_b   = (const float*)d_in[9];
    const float* h1_w    = (const float*)d_in[10];
    const float* h1_b    = (const float*)d_in[11];
    const float* h2_w    = (const float*)d_in[12];
    const float* h2_b    = (const float*)d_in[13];
    const float* h3_w    = (const float*)d_in[14];
    const float* h3_b    = (const float*)d_in[15];
    const float* Bp      = (const float*)d_in[16];
    float* out = (float*)d_out;

    k_front<<<PACKB + GEMVB, 256>>>(x, enc1_w, dec_w, enc1_b,
                                    enc2_w, enc2_b, h1_w, h1_b,
                                    h2_w, h2_b, h3_w, h3_b);
    k_back<<<GATHER_BLOCKS, 256>>>(nb_id, nb_dist, labels, dec_b, Bp, dec_w, out);
}

// round 16
// speedup vs baseline: 1.0532x; 1.0532x over previous
#include <cuda_runtime.h>
#include <cuda_fp16.h>
#include <math.h>

#define NNODES 50000
#define KNB 32
#define NLAT 10
#define NB 4
#define NCHUNK 10
#define QROW 12500        // float4 quads per 50000-float row
#define QCHW 1250         // quads per split-K chunk (12500/10)
#define PACKB 196         // pack blocks (ceil(50000/256))
#define GEMVB 250         // gemv blocks (25 u-groups x 10 chunks)
#define GATHER_BLOCKS 782 // ceil(50000 / 64)
#define WARMQ 5780        // float4 quads of MLP weights to stream through L2

__device__ uint4 g_decwr[NNODES * 2];       // fp16-packed dec_w rows (32B/row)
__device__ float g_part[NCHUNK * 800];      // GEMV partials [chunk][b*200+u]
__device__ float g_Htab[NB * 256];          // sigmoid table per (b, cluster)
__device__ float g_e[NB * NLAT];            // latent e
__device__ float g_sink[WARMQ];             // L2-warm sink (deterministic)

__device__ __forceinline__ float2 h2f(unsigned u) {
    __half2 h = *reinterpret_cast<__half2*>(&u);
    return __half22float2(h);
}

__device__ __forceinline__ float fsigmoid(float v) {
    return 1.0f / (1.0f + __expf(-v));
}

// ---------------------------------------------------------------- k_front
// Blocks 0..195:   pack dec_w to fp16 + stream MLP weights through L2.
// Blocks 196..445: gemv split-K partials (warp-per-u, 8 u per block).
__global__ __launch_bounds__(256) void k_front(
        const float* __restrict__ x,   const float* __restrict__ w,
        const float* __restrict__ dec_w,
        const float* __restrict__ enc2_w,
        const float* __restrict__ h1_w, const float* __restrict__ h2_w,
        const float* __restrict__ h3_w) {
    int tid = threadIdx.x;

    if (blockIdx.x < PACKB) {
        int n = blockIdx.x * 256 + tid;
        if (n < NNODES) {
            const float2* rp = (const float2*)(dec_w + n * NLAT);
            float2 a = __ldg(rp), b = __ldg(rp + 1), c = __ldg(rp + 2),
                   d = __ldg(rp + 3), e = __ldg(rp + 4);
            __half2 p0 = __float22half2_rn(a), p1 = __float22half2_rn(b),
                    p2 = __float22half2_rn(c), p3 = __float22half2_rn(d),
                    p4 = __float22half2_rn(e);
            uint4 lo = make_uint4(*(unsigned*)&p0, *(unsigned*)&p1,
                                  *(unsigned*)&p2, *(unsigned*)&p3);
            g_decwr[2 * n] = lo;
            ((uint2*)g_decwr)[4 * n + 2] = make_uint2(*(unsigned*)&p4, 0u);
        }
        if (n < WARMQ) {
            float4 v;
            if (n < 4096)       v = __ldg((const float4*)h3_w + n);
            else if (n < 5120)  v = __ldg((const float4*)h2_w + (n - 4096));
            else if (n < 5620)  v = __ldg((const float4*)enc2_w + (n - 5120));
            else                v = __ldg((const float4*)h1_w + (n - 5620));
            g_sink[n] = (v.x + v.y) + (v.z + v.w);
        }
        return;
    }

    int gid = blockIdx.x - PACKB;
    int warp = tid >> 5, lane = tid & 31;
    int ug = gid % 25, c = gid / 25;
    int u = ug * 8 + warp;
    int q0 = c * QCHW;

    const float4* x4 = (const float4*)x;
    const float4* w4 = (const float4*)w + (size_t)u * QROW;

    float a0 = 0.0f, a1 = 0.0f, a2 = 0.0f, a3 = 0.0f;

#pragma unroll 2
    for (int q = q0 + lane; q < q0 + QCHW; q += 32) {
        float4 wv = __ldg(w4 + q);
        float4 x0 = __ldg(x4 + q);
        float4 x1 = __ldg(x4 + QROW + q);
        float4 x2 = __ldg(x4 + 2 * QROW + q);
        float4 x3 = __ldg(x4 + 3 * QROW + q);
        a0 = fmaf(wv.x, x0.x, a0); a0 = fmaf(wv.y, x0.y, a0);
        a0 = fmaf(wv.z, x0.z, a0); a0 = fmaf(wv.w, x0.w, a0);
        a1 = fmaf(wv.x, x1.x, a1); a1 = fmaf(wv.y, x1.y, a1);
        a1 = fmaf(wv.z, x1.z, a1); a1 = fmaf(wv.w, x1.w, a1);
        a2 = fmaf(wv.x, x2.x, a2); a2 = fmaf(wv.y, x2.y, a2);
        a2 = fmaf(wv.z, x2.z, a2); a2 = fmaf(wv.w, x2.w, a2);
        a3 = fmaf(wv.x, x3.x, a3); a3 = fmaf(wv.y, x3.y, a3);
        a3 = fmaf(wv.z, x3.z, a3); a3 = fmaf(wv.w, x3.w, a3);
    }

#pragma unroll
    for (int o = 16; o; o >>= 1) {
        a0 += __shfl_down_sync(0xffffffffu, a0, o);
        a1 += __shfl_down_sync(0xffffffffu, a1, o);
        a2 += __shfl_down_sync(0xffffffffu, a2, o);
        a3 += __shfl_down_sync(0xffffffffu, a3, o);
    }
    if (lane == 0) {
        float* p = g_part + c * 800 + u;
        p[0]   = a0;
        p[200] = a1;
        p[400] = a2;
        p[600] = a3;
    }
}

// ---------------------------------------------------------------- k_mid
// Whole tiny-MLP chain, one block of 1024 threads (max stage parallelism,
// no register cap so load batching can hide L2 latency).
__global__ void k_mid(const float* __restrict__ enc1_b,
                      const float* __restrict__ enc2_w, const float* __restrict__ enc2_b,
                      const float* __restrict__ h1_w,  const float* __restrict__ h1_b,
                      const float* __restrict__ h2_w,  const float* __restrict__ h2_b,
                      const float* __restrict__ h3_w,  const float* __restrict__ h3_b) {
    __shared__ float sz[800];
    __shared__ float se[40];
    __shared__ float sh1[256];
    __shared__ float sh2[256];
    int tid = threadIdx.x;

    // stage 1: reduce the 10 gemv partial chunks, + bias, silu (200 threads x f4)
    if (tid < 200) {
        const float4* p = (const float4*)g_part;
        float4 s = p[tid];
#pragma unroll
        for (int cc = 1; cc < NCHUNK; cc++) {
            float4 v = p[cc * 200 + tid];
            s.x += v.x; s.y += v.y; s.z += v.z; s.w += v.w;
        }
        float sv[4] = {s.x, s.y, s.z, s.w};
#pragma unroll
        for (int j = 0; j < 4; j++) {
            int idx = tid * 4 + j;
            float t = sv[j] + enc1_b[idx % 200];
            sz[idx] = t * fsigmoid(t);              // silu
        }
    }
    __syncthreads();

    // stage 2: e = z @ enc2_w.T  (40 outputs x 16 lanes, 3-4 quads each)
    if (tid < 640) {
        int g = tid >> 4, r = tid & 15;
        int b = g / 10, v = g - b * 10;
        const float4* wrow = (const float4*)(enc2_w + v * 200);
        const float* zb = sz + b * 200;
        float s = 0.0f;
        for (int q = r; q < 50; q += 16) {
            float4 wv = __ldg(wrow + q);
            s = fmaf(wv.x, zb[4 * q + 0], s);
            s = fmaf(wv.y, zb[4 * q + 1], s);
            s = fmaf(wv.z, zb[4 * q + 2], s);
            s = fmaf(wv.w, zb[4 * q + 3], s);
        }
#pragma unroll
        for (int o = 8; o; o >>= 1) s += __shfl_down_sync(0xffffffffu, s, o, 16);
        if (r == 0) {
            s += enc2_b[v];
            se[g] = s;
            g_e[g] = s;
        }
    }
    __syncthreads();

    // stage 3: h1 (256 outputs, float2 weight loads)
    if (tid < 256) {
        int b = tid >> 6, m = tid & 63;
        const float2* wrow = (const float2*)(h1_w + m * 10);
        float2 w0 = __ldg(wrow), w1 = __ldg(wrow + 1), w2 = __ldg(wrow + 2),
               w3 = __ldg(wrow + 3), w4 = __ldg(wrow + 4);
        const float* eb = se + b * 10;
        float s = h1_b[m];
        s = fmaf(w0.x, eb[0], s); s = fmaf(w0.y, eb[1], s);
        s = fmaf(w1.x, eb[2], s); s = fmaf(w1.y, eb[3], s);
        s = fmaf(w2.x, eb[4], s); s = fmaf(w2.y, eb[5], s);
        s = fmaf(w3.x, eb[6], s); s = fmaf(w3.y, eb[7], s);
        s = fmaf(w4.x, eb[8], s); s = fmaf(w4.y, eb[9], s);
        sh1[tid] = s * fsigmoid(s);
    }
    __syncthreads();

    // stage 4: h2 (256 outputs, 16 independent f4 loads each)
    if (tid < 256) {
        int b = tid >> 6, m = tid & 63;
        const float4* wrow = (const float4*)(h2_w + m * 64);
        const float* hb = sh1 + b * 64;
        float s = h2_b[m];
#pragma unroll
        for (int q = 0; q < 16; q++) {
            float4 wv = __ldg(wrow + q);
            s = fmaf(wv.x, hb[4 * q + 0], s);
            s = fmaf(wv.y, hb[4 * q + 1], s);
            s = fmaf(wv.z, hb[4 * q + 2], s);
            s = fmaf(wv.w, hb[4 * q + 3], s);
        }
        sh2[tid] = s * fsigmoid(s);
    }
    __syncthreads();

    // stage 5: h3 + sigmoid table (1024 outputs, one thread each)
    {
        int b = tid >> 8, cc = tid & 255;
        const float4* wrow = (const float4*)(h3_w + cc * 64);
        const float* hb = sh2 + b * 64;
        float s = h3_b[cc];
#pragma unroll
        for (int q = 0; q < 16; q++) {
            float4 wv = __ldg(wrow + q);
            s = fmaf(wv.x, hb[4 * q + 0], s);
            s = fmaf(wv.y, hb[4 * q + 1], s);
            s = fmaf(wv.z, hb[4 * q + 2], s);
            s = fmaf(wv.w, hb[4 * q + 3], s);
        }
        g_Htab[tid] = fsigmoid(0.005f * s);
    }
}

// ---------------------------------------------------------------- k_back
// Gather + combine fused. Montgomery batch inversion: 1 reciprocal per
// lane instead of 10 (MUFU count per node 40 -> 4).
__global__ __launch_bounds__(256) void k_back(const int* __restrict__ nb_id,
                                              const float* __restrict__ nb_dist,
                                              const int* __restrict__ labels,
                                              const float* __restrict__ dec_b,
                                              const float* __restrict__ Bparam,
                                              const float* __restrict__ dec_w,
                                              float* __restrict__ out) {
    __shared__ float se[NB * NLAT];
    int tid = threadIdx.x;
    if (tid < NB * NLAT) se[tid] = g_e[tid];
    __syncthreads();

    int sub = tid & 3;
    int node = blockIdx.x * 64 + (tid >> 2);
    bool valid = (node < NNODES);
    int cnode = valid ? node : (NNODES - 1);

    float A[NLAT], Bv[NLAT];
#pragma unroll
    for (int l = 0; l < NLAT; l++) { A[l] = 0.0f; Bv[l] = 0.0f; }
    float S0 = 0.0f, d2max = 0.0f;

    const int4*   idp = (const int4*)(nb_id + cnode * KNB) + sub * 2;
    const float4* dp  = (const float4*)(nb_dist + cnode * KNB) + sub * 2;
#pragma unroll
    for (int kq = 0; kq < 2; kq++) {
        int4   iv = __ldg(idp + kq);
        float4 dv = __ldg(dp + kq);
        int   ida[4] = {iv.x, iv.y, iv.z, iv.w};
        float da[4]  = {dv.x, dv.y, dv.z, dv.w};
#pragma unroll
        for (int j = 0; j < 4; j++) {
            float d2 = da[j] * da[j];
            S0 += d2;
            d2max = fmaxf(d2max, d2);
            uint4 lo = __ldg(&g_decwr[2 * ida[j]]);
            uint2 hi = __ldg((const uint2*)g_decwr + 4 * ida[j] + 2);
            float2 f0 = h2f(lo.x), f1 = h2f(lo.y), f2 = h2f(lo.z),
                   f3 = h2f(lo.w), f4 = h2f(hi.x);
            float r[NLAT] = {f0.x, f0.y, f1.x, f1.y, f2.x,
                             f2.y, f3.x, f3.y, f4.x, f4.y};
#pragma unroll
            for (int l = 0; l < NLAT; l++) {
                A[l] += r[l];
                Bv[l] = fmaf(d2, r[l], Bv[l]);
            }
        }
    }

#pragma unroll
    for (int off = 1; off < 4; off <<= 1) {
#pragma unroll
        for (int l = 0; l < NLAT; l++) {
            A[l]  += __shfl_xor_sync(0xffffffffu, A[l],  off);
            Bv[l] += __shfl_xor_sync(0xffffffffu, Bv[l], off);
        }
        S0 += __shfl_xor_sync(0xffffffffu, S0, off);
        d2max = fmaxf(d2max, __shfl_xor_sync(0xffffffffu, d2max, off));
    }

    if (!valid) return;

    int b = sub;                       // lane handles batch b
    int label = __ldg(&labels[node]);
    float Bp = __ldg(Bparam);
    float invB2 = __fdividef(1.0f, Bp * Bp);
    float H = __ldg(&g_Htab[b * 256 + label]);
    float base = 1.0f - 0.5f * H;
    float ib = __fdividef(1.0f, base * base);
    float ib2 = ib * ib;
    float ib4 = ib2 * ib2;
    float inv9 = invB2 * ib4 * ib4 * ib2;

    float o = 0.0f;
    if (inv9 * d2max <= 1.0f) {
        // fast path: compute all s_l, t_l; one reciprocal via prefix/suffix
        float sarr[NLAT], tnum[NLAT], pre[NLAT];
        float iw = invB2;
#pragma unroll
        for (int l = 0; l < NLAT; l++) {
            iw *= ib;
            sarr[l] = fmaf(-iw, S0, (float)KNB);
            tnum[l] = fmaf(-iw, Bv[l], A[l]);
        }
        pre[0] = sarr[0];
#pragma unroll
        for (int l = 1; l < NLAT; l++) pre[l] = pre[l - 1] * sarr[l];
        float invP = __fdividef(1.0f, pre[NLAT - 1]);
        float suf = 1.0f;
#pragma unroll
        for (int l = NLAT - 1; l >= 0; l--) {
            float inv_sl = (l ? pre[l - 1] : 1.0f) * suf * invP;
            o = fmaf(se[b * NLAT + l] * tnum[l], inv_sl, o);
            suf *= sarr[l];
        }
    } else {
        // exact fallback with clamping (fp32 dec_w; practically never taken)
        float iw = invB2;
        for (int l = 0; l < NLAT; l++) {
            iw *= ib;
            float ss = 0.0f, tt = 0.0f;
            for (int k = 0; k < KNB; k++) {
                int id = __ldg(nb_id + node * KNB + k);
                float d = __ldg(nb_dist + node * KNB + k);
                float d2 = d * d;
                float win = fmaxf(0.0f, fmaf(-iw, d2, 1.0f));
                ss += win;
                tt = fmaf(__ldg(&dec_w[id * NLAT + l]), win, tt);
            }
            o = fmaf(se[b * NLAT + l], __fdividef(tt, ss), o);
        }
    }

    out[b * NNODES + node] = o + __ldg(&dec_b[node]);
}

// ---------------------------------------------------------------- launch
extern "C" void kernel_launch(void* const* d_in, const int* in_sizes, int n_in,
                              void* d_out, int out_size) {
    const float* x       = (const float*)d_in[0];
    const int*   nb_id   = (const int*)  d_in[1];
    const float* nb_dist = (const float*)d_in[2];
    const int*   labels  = (const int*)  d_in[3];
    const float* enc1_w  = (const float*)d_in[4];
    const float* enc1_b  = (const float*)d_in[5];
    const float* enc2_w  = (const float*)d_in[6];
    const float* enc2_b  = (const float*)d_in[7];
    const float* dec_w   = (const float*)d_in[8];
    const float* dec_b   = (const float*)d_in[9];
    const float* h1_w    = (const float*)d_in[10];
    const float* h1_b    = (const float*)d_in[11];
    const float* h2_w    = (const float*)d_in[12];
    const float* h2_b    = (const float*)d_in[13];
    const float* h3_w    = (const float*)d_in[14];
    const float* h3_b    = (const float*)d_in[15];
    const float* Bp      = (const float*)d_in[16];
    float* out = (float*)d_out;

    k_front<<<PACKB + GEMVB, 256>>>(x, enc1_w, dec_w, enc2_w, h1_w, h2_w, h3_w);
    k_mid<<<1, 1024>>>(enc1_b, enc2_w, enc2_b, h1_w, h1_b, h2_w, h2_b, h3_w, h3_b);
    k_back<<<GATHER_BLOCKS, 256>>>(nb_id, nb_dist, labels, dec_b, Bp, dec_w, out);
}

// round 17
// speedup vs baseline: 1.0690x; 1.0150x over previous
#include <cuda_runtime.h>
#include <cuda_fp16.h>
#include <math.h>

#define NNODES 50000
#define KNB 32
#define NLAT 10
#define NB 4
#define NCHUNK 50
#define QROW 12500        // float4 quads per 50000-float row
#define QCHW 250          // quads per split-K chunk (12500/50)
#define PACKB 196         // pack blocks (ceil(50000/256))
#define GEMVB 1250        // gemv blocks (25 u-groups x 50 chunks)
#define GATHER_BLOCKS 782 // ceil(50000 / 64)
#define WARMQ 5780        // float4 quads of MLP weights to stream through L2

__device__ uint4 g_decwr[NNODES * 2];       // fp16-packed dec_w rows (32B/row)
__device__ float g_part[NCHUNK * 800];      // GEMV partials [chunk][b*200+u]
__device__ float g_Htab[NB * 256];          // sigmoid table per (b, cluster)
__device__ float g_e[NB * NLAT];            // latent e
__device__ float g_sink[WARMQ];             // L2-warm sink (deterministic)

__device__ __forceinline__ float2 h2f(unsigned u) {
    __half2 h = *reinterpret_cast<__half2*>(&u);
    return __half22float2(h);
}

__device__ __forceinline__ float fsigmoid(float v) {
    return 1.0f / (1.0f + __expf(-v));
}

// ---------------------------------------------------------------- k_front
// Blocks 0..195:    pack dec_w to fp16 + stream MLP weights through L2.
// Blocks 196..1445: gemv split-K partials (warp-per-u, 8 u per block,
//                   50 chunks so ~34 warps/SM stream the 40MB of enc1_w).
__global__ __launch_bounds__(256) void k_front(
        const float* __restrict__ x,   const float* __restrict__ w,
        const float* __restrict__ dec_w,
        const float* __restrict__ enc2_w,
        const float* __restrict__ h1_w, const float* __restrict__ h2_w,
        const float* __restrict__ h3_w) {
    int tid = threadIdx.x;

    if (blockIdx.x < PACKB) {
        int n = blockIdx.x * 256 + tid;
        if (n < NNODES) {
            const float2* rp = (const float2*)(dec_w + n * NLAT);
            float2 a = __ldg(rp), b = __ldg(rp + 1), c = __ldg(rp + 2),
                   d = __ldg(rp + 3), e = __ldg(rp + 4);
            __half2 p0 = __float22half2_rn(a), p1 = __float22half2_rn(b),
                    p2 = __float22half2_rn(c), p3 = __float22half2_rn(d),
                    p4 = __float22half2_rn(e);
            uint4 lo = make_uint4(*(unsigned*)&p0, *(unsigned*)&p1,
                                  *(unsigned*)&p2, *(unsigned*)&p3);
            g_decwr[2 * n] = lo;
            ((uint2*)g_decwr)[4 * n + 2] = make_uint2(*(unsigned*)&p4, 0u);
        }
        if (n < WARMQ) {
            float4 v;
            if (n < 4096)       v = __ldg((const float4*)h3_w + n);
            else if (n < 5120)  v = __ldg((const float4*)h2_w + (n - 4096));
            else if (n < 5620)  v = __ldg((const float4*)enc2_w + (n - 5120));
            else                v = __ldg((const float4*)h1_w + (n - 5620));
            g_sink[n] = (v.x + v.y) + (v.z + v.w);
        }
        return;
    }

    int gid = blockIdx.x - PACKB;
    int warp = tid >> 5, lane = tid & 31;
    int ug = gid % 25, c = gid / 25;
    int u = ug * 8 + warp;
    int q0 = c * QCHW;

    const float4* x4 = (const float4*)x;
    const float4* w4 = (const float4*)w + (size_t)u * QROW;

    float a0 = 0.0f, a1 = 0.0f, a2 = 0.0f, a3 = 0.0f;

#pragma unroll 2
    for (int q = q0 + lane; q < q0 + QCHW; q += 32) {
        float4 wv = __ldg(w4 + q);
        float4 x0 = __ldg(x4 + q);
        float4 x1 = __ldg(x4 + QROW + q);
        float4 x2 = __ldg(x4 + 2 * QROW + q);
        float4 x3 = __ldg(x4 + 3 * QROW + q);
        a0 = fmaf(wv.x, x0.x, a0); a0 = fmaf(wv.y, x0.y, a0);
        a0 = fmaf(wv.z, x0.z, a0); a0 = fmaf(wv.w, x0.w, a0);
        a1 = fmaf(wv.x, x1.x, a1); a1 = fmaf(wv.y, x1.y, a1);
        a1 = fmaf(wv.z, x1.z, a1); a1 = fmaf(wv.w, x1.w, a1);
        a2 = fmaf(wv.x, x2.x, a2); a2 = fmaf(wv.y, x2.y, a2);
        a2 = fmaf(wv.z, x2.z, a2); a2 = fmaf(wv.w, x2.w, a2);
        a3 = fmaf(wv.x, x3.x, a3); a3 = fmaf(wv.y, x3.y, a3);
        a3 = fmaf(wv.z, x3.z, a3); a3 = fmaf(wv.w, x3.w, a3);
    }

#pragma unroll
    for (int o = 16; o; o >>= 1) {
        a0 += __shfl_down_sync(0xffffffffu, a0, o);
        a1 += __shfl_down_sync(0xffffffffu, a1, o);
        a2 += __shfl_down_sync(0xffffffffu, a2, o);
        a3 += __shfl_down_sync(0xffffffffu, a3, o);
    }
    if (lane == 0) {
        float* p = g_part + c * 800 + u;
        p[0]   = a0;
        p[200] = a1;
        p[400] = a2;
        p[600] = a3;
    }
}

// ---------------------------------------------------------------- k_mid
// Whole tiny-MLP chain, one block of 1024 threads.
__global__ void k_mid(const float* __restrict__ enc1_b,
                      const float* __restrict__ enc2_w, const float* __restrict__ enc2_b,
                      const float* __restrict__ h1_w,  const float* __restrict__ h1_b,
                      const float* __restrict__ h2_w,  const float* __restrict__ h2_b,
                      const float* __restrict__ h3_w,  const float* __restrict__ h3_b) {
    __shared__ float sz[800];
    __shared__ float se[40];
    __shared__ float sh1[256];
    __shared__ float sh2[256];
    int tid = threadIdx.x;

    // stage 1: reduce the 50 gemv partial chunks, + bias, silu (200 thr x f4)
    if (tid < 200) {
        const float4* p = (const float4*)g_part;
        float4 s = p[tid];
#pragma unroll 7
        for (int cc = 1; cc < NCHUNK; cc++) {
            float4 v = p[cc * 200 + tid];
            s.x += v.x; s.y += v.y; s.z += v.z; s.w += v.w;
        }
        float sv[4] = {s.x, s.y, s.z, s.w};
#pragma unroll
        for (int j = 0; j < 4; j++) {
            int idx = tid * 4 + j;
            float t = sv[j] + enc1_b[idx % 200];
            sz[idx] = t * fsigmoid(t);              // silu
        }
    }
    __syncthreads();

    // stage 2: e = z @ enc2_w.T  (40 outputs x 16 lanes)
    if (tid < 640) {
        int g = tid >> 4, r = tid & 15;
        int b = g / 10, v = g - b * 10;
        const float4* wrow = (const float4*)(enc2_w + v * 200);
        const float* zb = sz + b * 200;
        float s = 0.0f;
        for (int q = r; q < 50; q += 16) {
            float4 wv = __ldg(wrow + q);
            s = fmaf(wv.x, zb[4 * q + 0], s);
            s = fmaf(wv.y, zb[4 * q + 1], s);
            s = fmaf(wv.z, zb[4 * q + 2], s);
            s = fmaf(wv.w, zb[4 * q + 3], s);
        }
#pragma unroll
        for (int o = 8; o; o >>= 1) s += __shfl_down_sync(0xffffffffu, s, o, 16);
        if (r == 0) {
            s += enc2_b[v];
            se[g] = s;
            g_e[g] = s;
        }
    }
    __syncthreads();

    // stage 3: h1 (256 outputs, float2 weight loads)
    if (tid < 256) {
        int b = tid >> 6, m = tid & 63;
        const float2* wrow = (const float2*)(h1_w + m * 10);
        float2 w0 = __ldg(wrow), w1 = __ldg(wrow + 1), w2 = __ldg(wrow + 2),
               w3 = __ldg(wrow + 3), w4 = __ldg(wrow + 4);
        const float* eb = se + b * 10;
        float s = h1_b[m];
        s = fmaf(w0.x, eb[0], s); s = fmaf(w0.y, eb[1], s);
        s = fmaf(w1.x, eb[2], s); s = fmaf(w1.y, eb[3], s);
        s = fmaf(w2.x, eb[4], s); s = fmaf(w2.y, eb[5], s);
        s = fmaf(w3.x, eb[6], s); s = fmaf(w3.y, eb[7], s);
        s = fmaf(w4.x, eb[8], s); s = fmaf(w4.y, eb[9], s);
        sh1[tid] = s * fsigmoid(s);
    }
    __syncthreads();

    // stage 4: h2 (256 outputs, 16 independent f4 loads each)
    if (tid < 256) {
        int b = tid >> 6, m = tid & 63;
        const float4* wrow = (const float4*)(h2_w + m * 64);
        const float* hb = sh1 + b * 64;
        float s = h2_b[m];
#pragma unroll
        for (int q = 0; q < 16; q++) {
            float4 wv = __ldg(wrow + q);
            s = fmaf(wv.x, hb[4 * q + 0], s);
            s = fmaf(wv.y, hb[4 * q + 1], s);
            s = fmaf(wv.z, hb[4 * q + 2], s);
            s = fmaf(wv.w, hb[4 * q + 3], s);
        }
        sh2[tid] = s * fsigmoid(s);
    }
    __syncthreads();

    // stage 5: h3 + sigmoid table (1024 outputs, one thread each)
    {
        int b = tid >> 8, cc = tid & 255;
        const float4* wrow = (const float4*)(h3_w + cc * 64);
        const float* hb = sh2 + b * 64;
        float s = h3_b[cc];
#pragma unroll
        for (int q = 0; q < 16; q++) {
            float4 wv = __ldg(wrow + q);
            s = fmaf(wv.x, hb[4 * q + 0], s);
            s = fmaf(wv.y, hb[4 * q + 1], s);
            s = fmaf(wv.z, hb[4 * q + 2], s);
            s = fmaf(wv.w, hb[4 * q + 3], s);
        }
        g_Htab[tid] = fsigmoid(0.005f * s);
    }
}

// ---------------------------------------------------------------- k_back
// Gather + combine fused; Montgomery batch inversion (1 reciprocal for the
// 10 window normalizations instead of 10).
__global__ __launch_bounds__(256) void k_back(const int* __restrict__ nb_id,
                                              const float* __restrict__ nb_dist,
                                              const int* __restrict__ labels,
                                              const float* __restrict__ dec_b,
                                              const float* __restrict__ Bparam,
                                              const float* __restrict__ dec_w,
                                              float* __restrict__ out) {
    __shared__ float se[NB * NLAT];
    int tid = threadIdx.x;
    if (tid < NB * NLAT) se[tid] = g_e[tid];
    __syncthreads();

    int sub = tid & 3;
    int node = blockIdx.x * 64 + (tid >> 2);
    bool valid = (node < NNODES);
    int cnode = valid ? node : (NNODES - 1);

    float A[NLAT], Bv[NLAT];
#pragma unroll
    for (int l = 0; l < NLAT; l++) { A[l] = 0.0f; Bv[l] = 0.0f; }
    float S0 = 0.0f, d2max = 0.0f;

    const int4*   idp = (const int4*)(nb_id + cnode * KNB) + sub * 2;
    const float4* dp  = (const float4*)(nb_dist + cnode * KNB) + sub * 2;
#pragma unroll
    for (int kq = 0; kq < 2; kq++) {
        int4   iv = __ldg(idp + kq);
        float4 dv = __ldg(dp + kq);
        int   ida[4] = {iv.x, iv.y, iv.z, iv.w};
        float da[4]  = {dv.x, dv.y, dv.z, dv.w};
#pragma unroll
        for (int j = 0; j < 4; j++) {
            float d2 = da[j] * da[j];
            S0 += d2;
            d2max = fmaxf(d2max, d2);
            uint4 lo = __ldg(&g_decwr[2 * ida[j]]);
            uint2 hi = __ldg((const uint2*)g_decwr + 4 * ida[j] + 2);
            float2 f0 = h2f(lo.x), f1 = h2f(lo.y), f2 = h2f(lo.z),
                   f3 = h2f(lo.w), f4 = h2f(hi.x);
            float r[NLAT] = {f0.x, f0.y, f1.x, f1.y, f2.x,
                             f2.y, f3.x, f3.y, f4.x, f4.y};
#pragma unroll
            for (int l = 0; l < NLAT; l++) {
                A[l] += r[l];
                Bv[l] = fmaf(d2, r[l], Bv[l]);
            }
        }
    }

#pragma unroll
    for (int off = 1; off < 4; off <<= 1) {
#pragma unroll
        for (int l = 0; l < NLAT; l++) {
            A[l]  += __shfl_xor_sync(0xffffffffu, A[l],  off);
            Bv[l] += __shfl_xor_sync(0xffffffffu, Bv[l], off);
        }
        S0 += __shfl_xor_sync(0xffffffffu, S0, off);
        d2max = fmaxf(d2max, __shfl_xor_sync(0xffffffffu, d2max, off));
    }

    if (!valid) return;

    int b = sub;                       // lane handles batch b
    int label = __ldg(&labels[node]);
    float Bp = __ldg(Bparam);
    float invB2 = __fdividef(1.0f, Bp * Bp);
    float H = __ldg(&g_Htab[b * 256 + label]);
    float base = 1.0f - 0.5f * H;
    float ib = __fdividef(1.0f, base * base);
    float ib2 = ib * ib;
    float ib4 = ib2 * ib2;
    float inv9 = invB2 * ib4 * ib4 * ib2;

    float o = 0.0f;
    if (inv9 * d2max <= 1.0f) {
        // fast path: all s_l, t_l; one reciprocal via prefix/suffix products
        float sarr[NLAT], tnum[NLAT], pre[NLAT];
        float iw = invB2;
#pragma unroll
        for (int l = 0; l < NLAT; l++) {
            iw *= ib;
            sarr[l] = fmaf(-iw, S0, (float)KNB);
            tnum[l] = fmaf(-iw, Bv[l], A[l]);
        }
        pre[0] = sarr[0];
#pragma unroll
        for (int l = 1; l < NLAT; l++) pre[l] = pre[l - 1] * sarr[l];
        float invP = __fdividef(1.0f, pre[NLAT - 1]);
        float suf = 1.0f;
#pragma unroll
        for (int l = NLAT - 1; l >= 0; l--) {
            float inv_sl = (l ? pre[l - 1] : 1.0f) * suf * invP;
            o = fmaf(se[b * NLAT + l] * tnum[l], inv_sl, o);
            suf *= sarr[l];
        }
    } else {
        // exact fallback with clamping (fp32 dec_w; practically never taken)
        float iw = invB2;
        for (int l = 0; l < NLAT; l++) {
            iw *= ib;
            float ss = 0.0f, tt = 0.0f;
            for (int k = 0; k < KNB; k++) {
                int id = __ldg(nb_id + node * KNB + k);
                float d = __ldg(nb_dist + node * KNB + k);
                float d2 = d * d;
                float win = fmaxf(0.0f, fmaf(-iw, d2, 1.0f));
                ss += win;
                tt = fmaf(__ldg(&dec_w[id * NLAT + l]), win, tt);
            }
            o = fmaf(se[b * NLAT + l], __fdividef(tt, ss), o);
        }
    }

    out[b * NNODES + node] = o + __ldg(&dec_b[node]);
}

// ---------------------------------------------------------------- launch
extern "C" void kernel_launch(void* const* d_in, const int* in_sizes, int n_in,
                              void* d_out, int out_size) {
    const float* x       = (const float*)d_in[0];
    const int*   nb_id   = (const int*)  d_in[1];
    const float* nb_dist = (const float*)d_in[2];
    const int*   labels  = (const int*)  d_in[3];
    const float* enc1_w  = (const float*)d_in[4];
    const float* enc1_b  = (const float*)d_in[5];
    const float* enc2_w  = (const float*)d_in[6];
    const float* enc2_b  = (const float*)d_in[7];
    const float* dec_w   = (const float*)d_in[8];
    const float* dec_b   = (const float*)d_in[9];
    const float* h1_w    = (const float*)d_in[10];
    const float* h1_b    = (const float*)d_in[11];
    const float* h2_w    = (const float*)d_in[12];
    const float* h2_b    = (const float*)d_in[13];
    const float* h3_w    = (const float*)d_in[14];
    const float* h3_b    = (const float*)d_in[15];
    const float* Bp      = (const float*)d_in[16];
    float* out = (float*)d_out;

    k_front<<<PACKB + GEMVB, 256>>>(x, enc1_w, dec_w, enc2_w, h1_w, h2_w, h3_w);
    k_mid<<<1, 1024>>>(enc1_b, enc2_w, enc2_b, h1_w, h1_b, h2_w, h2_b, h3_w, h3_b);
    k_back<<<GATHER_BLOCKS, 256>>>(nb_id, nb_dist, labels, dec_b, Bp, dec_w, out);
}